// round 5
// baseline (speedup 1.0000x reference)
#include <cuda_runtime.h>

// Guided filter r=3, fused, tile 32x48, float2-packed smem planes,
// re-read sliding windows in H1 (no input rings -> fits 64 regs, 4 CTAs/SM).

#define NT 256
#define WD 1024
#define HD 1024
#define HWC (1024 * 1024)
#define TW 32
#define TH 48
#define ABR 54            // TH + 6 (a/b rows)
#define VP2 45            // v-plane pitch in float2 (44 cols used)
#define HP2 33            // hs-plane pitch in float2 (32 cols used)
#define INV49 (1.0f / 49.0f)
#define EPS_GF 1e-6f

#define N_F2 (2 * ABR * VP2 + ABR * HP2)   // 2*2430 + 1782 = 6642
#define SMEM_BYTES (N_F2 * 8)              // 53136 B -> 4 CTAs/SM

__global__ void __launch_bounds__(NT, 4)
gf_kernel(const float* __restrict__ gI,
          const float* __restrict__ gP,
          float* __restrict__ gOut) {
    extern __shared__ float2 sm2[];
    float2* pA = sm2;                    // (vI, vII)   vertical 7-sums
    float2* pB = sm2 + ABR * VP2;        // (vp, vIp)
    float2* pH = sm2 + 2 * ABR * VP2;    // (hsA, hsB)  horizontal 7-sums of a,b

    const int tid = threadIdx.x;
    const int bx = blockIdx.x, by = blockIdx.y, bz = blockIdx.z;
    const int x0 = bx * TW, y0 = by * TH;
    const float* Ib = gI + (size_t)bz * HWC;

#pragma unroll
    for (int ch = 0; ch < 3; ch++) {
        const float* Pb = gP + ((size_t)bz * 3 + ch) * HWC;

        // ---------- V1: vertical 7-sums of {p, I*p} (+ {I, I*I} on ch0) ----
        // thread = (v-column vx in [0,44), segment in [0,5)); 11 ab-rows/seg
        if (tid < 220) {
            int seg = tid / 44;
            int vx  = tid - seg * 44;
            int gxv = x0 + vx - 6;
            bool xok = (unsigned)gxv < (unsigned)WD;
            int gyr0 = y0 + seg * 11 - 6;
            int yab = seg * 11;
            float iv7[7], pv7[7];
            float sI = 0.f, sII = 0.f, sp = 0.f, sIp = 0.f;
#pragma unroll
            for (int k = 0; k < 7; k++) { iv7[k] = 0.f; pv7[k] = 0.f; }
#pragma unroll
            for (int t = 0; t < 17; t++) {
                int gyr = gyr0 + t;
                float iv = 0.f, pv = 0.f;
                if (xok && (unsigned)gyr < (unsigned)HD) {
                    size_t off = (size_t)gyr * WD + gxv;
                    iv = Ib[off];
                    pv = Pb[off];
                }
                int k = t % 7;
                float oi = iv7[k], oq = pv7[k];
                if (ch == 0) {
                    sI  += iv - oi;
                    sII += iv * iv - oi * oi;
                }
                sp  += pv - oq;
                sIp += iv * pv - oi * oq;
                iv7[k] = iv; pv7[k] = pv;
                if (t >= 6) {
                    int ar = yab + t - 6;
                    if (ar < ABR) {
                        if (ch == 0) pA[ar * VP2 + vx] = make_float2(sI, sII);
                        pB[ar * VP2 + vx] = make_float2(sp, sIp);
                    }
                }
            }
        }
        __syncthreads();

        // ---------- H1: h-sums -> a,b -> h-sums of a,b (fused, re-read) ----
        // thread = (chunk c in [0,4), ab-row ya in [0,54)); 8 out-x each
        if (tid < 216) {
            int c  = tid / 54;
            int ya = tid - c * 54;
            int gya = y0 + ya - 3;
            bool yok = (unsigned)gya < (unsigned)HD;
            int vxb = 8 * c;
            int row = ya * VP2;
            int gxb = x0 + vxb - 9;
            float wa7[7], wb7[7];
            float s0 = 0.f, s1 = 0.f, s2 = 0.f, s3 = 0.f, sA = 0.f, sB = 0.f;
#pragma unroll
            for (int k = 0; k < 7; k++) { wa7[k] = 0.f; wb7[k] = 0.f; }
#pragma unroll
            for (int t = 0; t < 20; t++) {
                int vx = vxb + t;            // max 43 < 44: always in-plane
                float2 nA = pA[row + vx];
                float2 nB = pB[row + vx];
                if (t < 7) {
                    s0 += nA.x; s1 += nA.y; s2 += nB.x; s3 += nB.y;
                } else {
                    float2 oA = pA[row + vx - 7];
                    float2 oB = pB[row + vx - 7];
                    s0 += nA.x - oA.x; s1 += nA.y - oA.y;
                    s2 += nB.x - oB.x; s3 += nB.y - oB.y;
                }
                if (t >= 6) {
                    float av = 0.f, bv = 0.f;
                    int gxa = gxb + t;
                    if (yok && (unsigned)gxa < (unsigned)WD) {
                        float mi  = s0 * INV49;
                        float mp  = s2 * INV49;
                        float var = fmaf(s1, INV49, -mi * mi);
                        float cov = fmaf(s3, INV49, -mi * mp);
                        av = cov * __fdividef(1.0f, var + EPS_GF);
                        bv = fmaf(-av, mi, mp);
                    }
                    int k = t % 7;
                    sA += av - wa7[k]; sB += bv - wb7[k];
                    wa7[k] = av; wb7[k] = bv;
                    if (t >= 12)
                        pH[ya * HP2 + (vxb + t - 12)] = make_float2(sA, sB);
                }
            }
        }
        __syncthreads();

        // ---------- V2: vertical 7-sum of hs + combine + store -------------
        // thread = (out-x ox in [0,32), segment in [0,8)); 6 out rows each
        {
            int ox  = tid & 31;
            int seg = tid >> 5;
            int ya0 = seg * 6;
            float wa7[7], wb7[7];
            float sA = 0.f, sB = 0.f;
#pragma unroll
            for (int k = 0; k < 7; k++) { wa7[k] = 0.f; wb7[k] = 0.f; }
            const int gx = x0 + ox;
            float* Ob = gOut + ((size_t)bz * 3 + ch) * HWC;
#pragma unroll
            for (int t = 0; t < 12; t++) {
                float2 h = pH[(ya0 + t) * HP2 + ox];
                int k = t % 7;
                sA += h.x - wa7[k]; sB += h.y - wb7[k];
                wa7[k] = h.x; wb7[k] = h.y;
                if (t >= 6) {
                    int gy = y0 + ya0 + t - 6;
                    if (gy < HD) {
                        size_t off = (size_t)gy * WD + gx;
                        float q = fmaf(sA * INV49, Ib[off], sB * INV49);
                        q = fminf(fmaxf(q, 0.0f), 1.0f);
                        Ob[off] = q;
                    }
                }
            }
        }
        // no sync needed here: V2 reads only pH; next V1 writes only pB/pA,
        // and the post-V1 barrier orders pH reuse.
    }
}

extern "C" void kernel_launch(void* const* d_in, const int* in_sizes, int n_in,
                              void* d_out, int out_size) {
    const float* I = (const float*)d_in[0];
    const float* p = (const float*)d_in[1];
    if (n_in >= 2 && in_sizes[0] > in_sizes[1]) {  // defensive: I is smaller
        const float* t = I; I = p; p = t;
    }
    float* out = (float*)d_out;

    cudaFuncSetAttribute(gf_kernel,
                         cudaFuncAttributeMaxDynamicSharedMemorySize, SMEM_BYTES);
    dim3 grid(WD / TW, (HD + TH - 1) / TH, 8);
    gf_kernel<<<grid, NT, SMEM_BYTES>>>(I, p, out);
}

// round 6
// speedup vs baseline: 1.4218x; 1.4218x over previous
#include <cuda_runtime.h>

// Guided filter r=3, fused, tile 32x44.
// Per-tile (mi, 1/(var+eps)) precompute; per-channel H1 reads only (vp,vIp)+M.
// pH aliases pA. 51.6KB smem -> 4 CTAs/SM.

#define NT 256
#define WD 1024
#define HD 1024
#define HWC (1024 * 1024)
#define TW 32
#define TH 44
#define ABR 50            // TH + 6
#define VP2 45            // pA/pB pitch in float2
#define MP2 39            // M pitch in float2 (38 cols used)
#define HP2 33            // pH pitch in float2 (32 cols used)
#define INV49 (1.0f / 49.0f)
#define EPS_GF 1e-6f

#define OFF_PB 0
#define OFF_PA (ABR * VP2)            // 2250 (also pH)
#define OFF_M  (2 * ABR * VP2)        // 4500
#define N_F2   (2 * ABR * VP2 + ABR * MP2)   // 4500 + 1950 = 6450
#define SMEM_BYTES (N_F2 * 8)                // 51600 -> 4 CTAs/SM

__global__ void __launch_bounds__(NT, 4)
gf_kernel(const float* __restrict__ gI,
          const float* __restrict__ gP,
          float* __restrict__ gOut) {
    extern __shared__ float2 sm2[];
    float2* pB = sm2 + OFF_PB;     // (vp, vIp) vertical 7-sums
    float2* pA = sm2 + OFF_PA;     // (vI, vII) vertical 7-sums (ch0 only)
    float2* pH = sm2 + OFF_PA;     // (hsA, hsB) — aliases pA after H1a
    float2* M  = sm2 + OFF_M;      // (mean_I, 1/(var+eps)) per ab-pixel

    const int tid = threadIdx.x;
    const int bx = blockIdx.x, by = blockIdx.y, bz = blockIdx.z;
    const int x0 = bx * TW, y0 = by * TH;
    const float* Ib = gI + (size_t)bz * HWC;

#pragma unroll
    for (int ch = 0; ch < 3; ch++) {
        const float* Pb = gP + ((size_t)bz * 3 + ch) * HWC;

        // ---------- V1: vertical 7-sums of {p, I*p} (+ {I,I*I} on ch0) ----
        // thread = (segment 0..4, v-col 0..43); 10 ab-rows per segment
        if (tid < 220) {
            int seg = tid / 44;
            int vx  = tid - seg * 44;
            int gxv = x0 + vx - 6;
            bool xok = (unsigned)gxv < (unsigned)WD;
            int gyr0 = y0 + seg * 10 - 6;
            int ya0 = seg * 10;
            float iv7[7], pv7[7];
            float sI = 0.f, sII = 0.f, sp = 0.f, sIp = 0.f;
#pragma unroll
            for (int k = 0; k < 7; k++) { iv7[k] = 0.f; pv7[k] = 0.f; }
#pragma unroll
            for (int t = 0; t < 16; t++) {
                int gyr = gyr0 + t;
                float iv = 0.f, pv = 0.f;
                if (xok && (unsigned)gyr < (unsigned)HD) {
                    size_t off = (size_t)gyr * WD + gxv;
                    iv = Ib[off];
                    pv = Pb[off];
                }
                int k = t % 7;
                float oi = iv7[k], oq = pv7[k];
                if (ch == 0) {
                    sI  += iv - oi;
                    sII += iv * iv - oi * oi;
                }
                sp  += pv - oq;
                sIp += iv * pv - oi * oq;
                iv7[k] = iv; pv7[k] = pv;
                if (t >= 6) {
                    int ar = ya0 + t - 6;            // <= 49
                    if (ch == 0) pA[ar * VP2 + vx] = make_float2(sI, sII);
                    pB[ar * VP2 + vx] = make_float2(sp, sIp);
                }
            }
        }
        __syncthreads();

        // ---------- H1a (per tile): h-sums of (vI,vII) -> (mi, rv) --------
        if (ch == 0) {
            // thread = (chunk 0..3, row 0..49); 10 ax per chunk (38 used)
            if (tid < 200) {
                int c  = tid / 50;
                int ya = tid - c * 50;
                int axb = c * 10;
                int row = ya * VP2;
                float w0[7], w1[7];
                float s0 = 0.f, s1 = 0.f;
#pragma unroll
                for (int k = 0; k < 7; k++) { w0[k] = 0.f; w1[k] = 0.f; }
#pragma unroll
                for (int t = 0; t < 16; t++) {
                    int vx = axb + t;
                    float2 A = (vx < 44) ? pA[row + vx] : make_float2(0.f, 0.f);
                    int k = t % 7;
                    s0 += A.x - w0[k]; s1 += A.y - w1[k];
                    w0[k] = A.x; w1[k] = A.y;
                    if (t >= 6) {
                        int ax = axb + t - 6;
                        if (ax < 38) {
                            float mi  = s0 * INV49;
                            float var = fmaf(s1, INV49, -mi * mi);
                            M[ya * MP2 + ax] =
                                make_float2(mi, __fdividef(1.0f, var + EPS_GF));
                        }
                    }
                }
            }
            __syncthreads();
        }

        // ---------- H1b: h-sums of (vp,vIp) -> a,b -> h-sums of a,b -------
        // thread = (chunk 0..3, row 0..49); 8 out-x per chunk
        if (tid < 200) {
            int c  = tid / 50;
            int ya = tid - c * 50;
            int oxb = c * 8;
            int gya = y0 + ya - 3;
            bool yok = (unsigned)gya < (unsigned)HD;
            int rowB = ya * VP2, rowM = ya * MP2, rowH = ya * HP2;
            float wp[7], wq[7], wa[7], wb[7];
            float s2 = 0.f, s3 = 0.f, sA = 0.f, sB = 0.f;
#pragma unroll
            for (int k = 0; k < 7; k++) {
                wp[k] = 0.f; wq[k] = 0.f; wa[k] = 0.f; wb[k] = 0.f;
            }
#pragma unroll
            for (int t = 0; t < 20; t++) {
                int vx = oxb + t;                    // <= 43: always valid
                float2 B = pB[rowB + vx];
                int k = t % 7;
                s2 += B.x - wp[k]; s3 += B.y - wq[k];
                wp[k] = B.x; wq[k] = B.y;
                if (t >= 6) {
                    int ax = oxb + t - 6;            // a-index, gx = x0+ax-3
                    float av = 0.f, bv = 0.f;
                    if (yok && (unsigned)(x0 + ax - 3) < (unsigned)WD) {
                        float2 m = M[rowM + ax];
                        float mp  = s2 * INV49;
                        float mip = s3 * INV49;
                        av = (mip - m.x * mp) * m.y;
                        bv = fmaf(-av, m.x, mp);
                    }
                    sA += av - wa[k]; sB += bv - wb[k];
                    wa[k] = av; wb[k] = bv;
                    if (t >= 12)
                        pH[rowH + (oxb + t - 12)] = make_float2(sA, sB);
                }
            }
        }
        __syncthreads();

        // ---------- V2: vertical 7-sum of hs + combine + store ------------
        // thread = (out-x 0..31, segment 0..7); 6 out rows per segment
        {
            int ox  = tid & 31;
            int seg = tid >> 5;
            int ya0 = seg * 6;
            float wa[7], wb[7];
            float sA = 0.f, sB = 0.f;
#pragma unroll
            for (int k = 0; k < 7; k++) { wa[k] = 0.f; wb[k] = 0.f; }
            const int gx = x0 + ox;
            float* Ob = gOut + ((size_t)bz * 3 + ch) * HWC;
#pragma unroll
            for (int t = 0; t < 12; t++) {
                int ar = ya0 + t;
                float2 h = (ar < ABR) ? pH[ar * HP2 + ox]
                                      : make_float2(0.f, 0.f);
                int k = t % 7;
                sA += h.x - wa[k]; sB += h.y - wb[k];
                wa[k] = h.x; wb[k] = h.y;
                if (t >= 6) {
                    int oy = ya0 + t - 6;
                    int gy = y0 + oy;
                    if (oy < TH && gy < HD) {
                        size_t off = (size_t)gy * WD + gx;
                        float q = fmaf(sA * INV49, Ib[off], sB * INV49);
                        q = fminf(fmaxf(q, 0.0f), 1.0f);
                        Ob[off] = q;
                    }
                }
            }
        }
        // No trailing sync: V2 reads pH; next V1 writes only pB (disjoint),
        // and the next post-V1 barrier orders the following pH overwrite.
    }
}

extern "C" void kernel_launch(void* const* d_in, const int* in_sizes, int n_in,
                              void* d_out, int out_size) {
    const float* I = (const float*)d_in[0];
    const float* p = (const float*)d_in[1];
    if (n_in >= 2 && in_sizes[0] > in_sizes[1]) {  // defensive: I is smaller
        const float* t = I; I = p; p = t;
    }
    float* out = (float*)d_out;

    cudaFuncSetAttribute(gf_kernel,
                         cudaFuncAttributeMaxDynamicSharedMemorySize, SMEM_BYTES);
    dim3 grid(WD / TW, (HD + TH - 1) / TH, 8);
    gf_kernel<<<grid, NT, SMEM_BYTES>>>(I, p, out);
}